// round 16
// baseline (speedup 1.0000x reference)
#include <cuda_runtime.h>
#include <cuda_fp16.h>
#include <cstdint>

// Problem dims (fixed by dataset)
#define MDIM 8192
#define NDIM 4096
#define KDIM 4096

#define TILE_M 256
#define TILE_N 128
#define KC 128                        // K per chunk (doubled: half the syncs)
#define NCHUNKS (KDIM / KC)           // 32
#define STAGES 2

#define A_STAGE_BYTES (TILE_M * KC * 2)               // 65536
#define B_STAGE_BYTES (TILE_N * KC * 2)               // 32768
#define STAGE_BYTES (A_STAGE_BYTES + B_STAGE_BYTES)   // 98304
#define BAR_BYTES 64
#define SMEM_BYTES (STAGES * STAGE_BYTES + BAR_BYTES) // 196672 -> 1 CTA/SM, 16 warps

// fp16 operand buffers (device globals; cudaMalloc forbidden)
__device__ __half g_A[(size_t)MDIM * KDIM];
__device__ __half g_B[(size_t)NDIM * KDIM];  // [N][K] (transposed w_t)

// ---------------------------------------------------------------------------
// Helpers
// ---------------------------------------------------------------------------
__device__ __forceinline__ uint32_t smem_u32(const void* p) {
    uint32_t a;
    asm("{ .reg .u64 t; cvta.to.shared.u64 t, %1; cvt.u32.u64 %0, t; }"
        : "=r"(a) : "l"(p));
    return a;
}

__device__ __forceinline__ void cp_async16(uint32_t dst, const void* src) {
    asm volatile("cp.async.cg.shared.global [%0], [%1], 16;" :: "r"(dst), "l"(src));
}
__device__ __forceinline__ void cp_commit() {
    asm volatile("cp.async.commit_group;" ::: "memory");
}

__device__ __forceinline__ void mbar_init(uint32_t bar, uint32_t cnt) {
    asm volatile("mbarrier.init.shared.b64 [%0], %1;" :: "r"(bar), "r"(cnt) : "memory");
}
__device__ __forceinline__ void mbar_arrive(uint32_t bar) {
    asm volatile("mbarrier.arrive.shared.b64 _, [%0];" :: "r"(bar) : "memory");
}
__device__ __forceinline__ void mbar_wait(uint32_t bar, uint32_t parity) {
    asm volatile(
        "{\n\t"
        ".reg .pred P;\n\t"
        "WAITL_%=:\n\t"
        "mbarrier.try_wait.parity.shared.b64 P, [%0], %1;\n\t"
        "@P bra.uni DONEL_%=;\n\t"
        "bra.uni WAITL_%=;\n\t"
        "DONEL_%=:\n\t"
        "}"
        :: "r"(bar), "r"(parity) : "memory");
}

__device__ __forceinline__ void ldsm_x4(uint32_t& r0, uint32_t& r1, uint32_t& r2, uint32_t& r3,
                                        uint32_t addr) {
    asm volatile("ldmatrix.sync.aligned.m8n8.x4.shared.b16 {%0,%1,%2,%3}, [%4];"
                 : "=r"(r0), "=r"(r1), "=r"(r2), "=r"(r3) : "r"(addr));
}

__device__ __forceinline__ void mma_16816(float& c0, float& c1, float& c2, float& c3,
                                          uint32_t a0, uint32_t a1, uint32_t a2, uint32_t a3,
                                          uint32_t b0, uint32_t b1) {
    asm volatile(
        "mma.sync.aligned.m16n8k16.row.col.f32.f16.f16.f32 "
        "{%0,%1,%2,%3}, {%4,%5,%6,%7}, {%8,%9}, {%0,%1,%2,%3};"
        : "+f"(c0), "+f"(c1), "+f"(c2), "+f"(c3)
        : "r"(a0), "r"(a1), "r"(a2), "r"(a3), "r"(b0), "r"(b1));
}

// ---------------------------------------------------------------------------
// Fused prep: fp32 -> fp16 for x (copy) and w_t (transpose to [N][K]).
// ---------------------------------------------------------------------------
#define XV4_PER_THREAD 8
#define XBLOCKS ((MDIM * (size_t)KDIM) / 4 / 256 / XV4_PER_THREAD)   // 4096
#define WBLOCKS ((NDIM / 64) * (KDIM / 64))                          // 4096

__global__ void prep_kernel(const float* __restrict__ x, const float* __restrict__ wt) {
    __shared__ float t[64][65];
    const unsigned b = blockIdx.x;
    const int tid = threadIdx.x;
    if (b < (unsigned)XBLOCKS) {
        const float4* x4 = reinterpret_cast<const float4*>(x);
        __half2* A2 = reinterpret_cast<__half2*>(g_A);
        size_t base = (size_t)b * 256 * XV4_PER_THREAD + tid;
        float4 v[XV4_PER_THREAD];
#pragma unroll
        for (int j = 0; j < XV4_PER_THREAD; j++)
            v[j] = x4[base + (size_t)j * 256];
#pragma unroll
        for (int j = 0; j < XV4_PER_THREAD; j++) {
            size_t i = base + (size_t)j * 256;
            A2[i * 2 + 0] = __floats2half2_rn(v[j].x, v[j].y);
            A2[i * 2 + 1] = __floats2half2_rn(v[j].z, v[j].w);
        }
    } else {
        const unsigned wb = b - (unsigned)XBLOCKS;
        const int n0 = (int)(wb % (NDIM / 64)) * 64;
        const int k0 = (int)(wb / (NDIM / 64)) * 64;
        const int tx = tid & 63;
        const int ty = tid >> 6;
#pragma unroll
        for (int j = 0; j < 16; j++)
            t[ty + j * 4][tx] = wt[(size_t)(k0 + ty + j * 4) * NDIM + n0 + tx];
        __syncthreads();
        const int nl = tid >> 3;
        const int kl = (tid & 7) * 8;
#pragma unroll
        for (int pass = 0; pass < 2; pass++) {
            const int n = nl + pass * 32;
            uint4 v;
            __half2 h0 = __floats2half2_rn(t[kl + 0][n], t[kl + 1][n]);
            __half2 h1 = __floats2half2_rn(t[kl + 2][n], t[kl + 3][n]);
            __half2 h2 = __floats2half2_rn(t[kl + 4][n], t[kl + 5][n]);
            __half2 h3 = __floats2half2_rn(t[kl + 6][n], t[kl + 7][n]);
            v.x = *reinterpret_cast<uint32_t*>(&h0);
            v.y = *reinterpret_cast<uint32_t*>(&h1);
            v.z = *reinterpret_cast<uint32_t*>(&h2);
            v.w = *reinterpret_cast<uint32_t*>(&h3);
            *reinterpret_cast<uint4*>(g_B + (size_t)(n0 + n) * KDIM + k0 + kl) = v;
        }
    }
}

// ---------------------------------------------------------------------------
// Single fp16 GEMM, fp32 accumulate — mbarrier pipeline, KC=128 (32 chunks:
// half the sync rounds of KC=64). CTA 256x128, 16 warps (4x4), warp tile
// 64x32, 2 stages (192KB smem, 1 CTA/SM, 16 warps/SM).
// SMEM rows are 256B (two 128B swizzle segments per row).
// Affine load offsets: a_sw[j]=a_sw0+j*8192, a_go[j]=a_go0+j*32*KDIM (j row
// blocks of 32), B = A-mapping + scalar delta — keeps regs under the 128 cap.
// ---------------------------------------------------------------------------
__global__ void __launch_bounds__(512, 1)
gemm_kernel(float* __restrict__ out) {
    extern __shared__ char smem[];
    const uint32_t sbase = smem_u32(smem);
    const uint32_t barb = sbase + STAGES * STAGE_BYTES;
    // barriers: full[s] at barb + s*16, empty[s] at barb + s*16 + 8

    const int tid = threadIdx.x;
    const int wid = tid >> 5;
    const int lid = tid & 31;
    const int wm = wid & 3;       // M offset wm*64
    const int wn = wid >> 2;      // N offset wn*32

    const int m0 = blockIdx.y * TILE_M;
    const int n0 = blockIdx.x * TILE_N;

    if (tid == 0) {
#pragma unroll
        for (int s = 0; s < STAGES; s++) {
            mbar_init(barb + s * 16, 512);      // full: every thread arrives
            mbar_init(barb + s * 16 + 8, 512);  // empty: every thread arrives
        }
    }

    // ---- load mapping (affine in j) ----
    // granule g = tid + j*512 covers 16B; r = g>>4 = (tid>>4) + 32j (exact,
    // 512 % 16 == 0); c16 = tid & 15 invariant. Row stride in smem = 256B,
    // two 128B swizzle segments per row. (r&7) invariant under r += 32.
    const int r0 = tid >> 4;
    const int c16 = tid & 15;
    const uint32_t a_sw0 = (uint32_t)(r0 * 256 + (c16 >> 3) * 128 +
                                      (((c16 & 7) * 16) ^ ((r0 & 7) << 4)));
    const int a_go0 = (m0 + r0) * KDIM + c16 * 8;     // element offset
    const int bdelta = (n0 - m0) * KDIM;              // B offset = A offset + bdelta

    // ---- ldmatrix per-lane address components ----
    const int a_row_l = lid & 15;
    const int a_kb_l = ((lid >> 4) & 1) * 16;
    const int b_row_l = (lid & 7) + ((lid >> 4) & 1) * 8;
    const int b_kb_l = ((lid >> 3) & 1) * 16;

    uint32_t a_rowterm[4], a_xr[4];
#pragma unroll
    for (int mf = 0; mf < 4; mf++) {
        int r = wm * 64 + mf * 16 + a_row_l;
        a_rowterm[mf] = (uint32_t)(r * 256);
        a_xr[mf] = (uint32_t)((r & 7) << 4);
    }
    uint32_t b_rowterm[2], b_xr[2];
#pragma unroll
    for (int p = 0; p < 2; p++) {
        int r = wn * 32 + p * 16 + b_row_l;
        b_rowterm[p] = (uint32_t)(A_STAGE_BYTES + r * 256);
        b_xr[p] = (uint32_t)((r & 7) << 4);
    }

    float acc[4][4][4];
#pragma unroll
    for (int i = 0; i < 4; i++)
#pragma unroll
        for (int j = 0; j < 4; j++)
#pragma unroll
            for (int q = 0; q < 4; q++) acc[i][j][q] = 0.f;

    auto issue_loads = [&](int cc) {
        const int k0 = cc * KC;
        const uint32_t stage = sbase + (uint32_t)(cc & 1) * STAGE_BYTES;
        // A: 8 row-blocks of 32 rows (256 rows total)
#pragma unroll
        for (int j = 0; j < 8; j++)
            cp_async16(stage + a_sw0 + (uint32_t)(j * 8192),
                       g_A + (a_go0 + j * 32 * KDIM + k0));
        // B: 4 row-blocks of 32 rows (128 rows total)
#pragma unroll
        for (int j = 0; j < 4; j++)
            cp_async16(stage + A_STAGE_BYTES + a_sw0 + (uint32_t)(j * 8192),
                       g_B + (a_go0 + bdelta + j * 32 * KDIM + k0));
        cp_commit();
    };

    __syncthreads();   // barrier init visible before any arrive

    // prologue: both stages in flight
    issue_loads(0);
    issue_loads(1);

    for (int c = 0; c < NCHUNKS; c++) {
        const uint32_t st = (uint32_t)(c & 1);
        const uint32_t ph = (uint32_t)((c >> 1) & 1);   // parity for stage st, use #c/2

        // retire chunk c's cp.async group (groups outstanding: c, c+1)
        if (c == NCHUNKS - 1)
            asm volatile("cp.async.wait_group 0;" ::: "memory");
        else
            asm volatile("cp.async.wait_group 1;" ::: "memory");
        mbar_arrive(barb + st * 16);            // full(c): this thread's slice retired

        // ---- consume chunk c ----
        mbar_wait(barb + st * 16, ph);

        const uint32_t stage = sbase + st * STAGE_BYTES;
#pragma unroll
        for (int ks = 0; ks < 8; ks++) {
            const uint32_t akb = (uint32_t)(a_kb_l + ks * 32);   // 0..255
            const uint32_t bkb = (uint32_t)(b_kb_l + ks * 32);
            const uint32_t a_off = ((akb & 127u)) , a_seg = (akb & 128u);
            const uint32_t b_off = ((bkb & 127u)) , b_seg = (bkb & 128u);

            uint32_t a[4][4];
            uint32_t b[2][4];
#pragma unroll
            for (int mf = 0; mf < 4; mf++)
                ldsm_x4(a[mf][0], a[mf][1], a[mf][2], a[mf][3],
                        stage + a_rowterm[mf] + a_seg + (a_off ^ a_xr[mf]));
#pragma unroll
            for (int p = 0; p < 2; p++)
                ldsm_x4(b[p][0], b[p][1], b[p][2], b[p][3],
                        stage + b_rowterm[p] + b_seg + (b_off ^ b_xr[p]));

            // Early stage release after the LAST smem read of this chunk.
            if (ks == 7)
                mbar_arrive(barb + st * 16 + 8);   // empty(c)

#pragma unroll
            for (int mf = 0; mf < 4; mf++)
#pragma unroll
                for (int nf = 0; nf < 4; nf++)
                    mma_16816(acc[mf][nf][0], acc[mf][nf][1], acc[mf][nf][2], acc[mf][nf][3],
                              a[mf][0], a[mf][1], a[mf][2], a[mf][3],
                              b[nf >> 1][(nf & 1) * 2], b[nf >> 1][(nf & 1) * 2 + 1]);
        }

        // ---- produce chunk c+2 into stage st (now released by all warps) ----
        if (c + 2 < NCHUNKS) {
            mbar_wait(barb + st * 16 + 8, ph);   // all warps done reading chunk c
            issue_loads(c + 2);
        }
    }

    // ---- epilogue: fp32 acc -> gmem ----
    const int row_base = m0 + wm * 64 + (lid >> 2);
    const int col_base = n0 + wn * 32 + (lid & 3) * 2;
#pragma unroll
    for (int mf = 0; mf < 4; mf++) {
#pragma unroll
        for (int nf = 0; nf < 4; nf++) {
            int r = row_base + mf * 16;
            int cl = col_base + nf * 8;
            float2* o0 = reinterpret_cast<float2*>(out + (size_t)r * NDIM + cl);
            float2* o1 = reinterpret_cast<float2*>(out + (size_t)(r + 8) * NDIM + cl);
            *o0 = make_float2(acc[mf][nf][0], acc[mf][nf][1]);
            *o1 = make_float2(acc[mf][nf][2], acc[mf][nf][3]);
        }
    }
}

// ---------------------------------------------------------------------------
// Launch
// ---------------------------------------------------------------------------
extern "C" void kernel_launch(void* const* d_in, const int* in_sizes, int n_in,
                              void* d_out, int out_size) {
    // Identify inputs by unique element counts: x = 8192*4096, w_t = 4096*4096
    const float* x = nullptr;
    const float* wt = nullptr;
    for (int i = 0; i < n_in; i++) {
        if (in_sizes[i] == 33554432) x = (const float*)d_in[i];
        else if (in_sizes[i] == 16777216) wt = (const float*)d_in[i];
    }

    cudaFuncSetAttribute(gemm_kernel, cudaFuncAttributeMaxDynamicSharedMemorySize, SMEM_BYTES);

    prep_kernel<<<(unsigned)(XBLOCKS + WBLOCKS), 256>>>(x, wt);
    gemm_kernel<<<dim3(NDIM / TILE_N, MDIM / TILE_M), 512, SMEM_BYTES>>>((float*)d_out);
}

// round 17
// speedup vs baseline: 1.0525x; 1.0525x over previous
#include <cuda_runtime.h>
#include <cuda_fp16.h>
#include <cstdint>

// Problem dims (fixed by dataset)
#define MDIM 8192
#define NDIM 4096
#define KDIM 4096

#define TILE_M 128
#define TILE_N 128
#define KC 64                         // K per chunk
#define NCHUNKS (KDIM / KC)           // 64
#define STAGES 3

#define A_STAGE_BYTES (TILE_M * KC * 2)               // 16384
#define B_STAGE_BYTES (TILE_N * KC * 2)               // 16384
#define STAGE_BYTES (A_STAGE_BYTES + B_STAGE_BYTES)   // 32768
#define BAR_BYTES 64
#define SMEM_BYTES (STAGES * STAGE_BYTES + BAR_BYTES) // 98368 -> 2 CTAs/SM

// fp16 operand buffers (device globals; cudaMalloc forbidden)
__device__ __half g_A[(size_t)MDIM * KDIM];
__device__ __half g_B[(size_t)NDIM * KDIM];  // [N][K] (transposed w_t)

// ---------------------------------------------------------------------------
// Helpers
// ---------------------------------------------------------------------------
__device__ __forceinline__ uint32_t smem_u32(const void* p) {
    uint32_t a;
    asm("{ .reg .u64 t; cvta.to.shared.u64 t, %1; cvt.u32.u64 %0, t; }"
        : "=r"(a) : "l"(p));
    return a;
}

__device__ __forceinline__ void cp_async16(uint32_t dst, const void* src) {
    asm volatile("cp.async.cg.shared.global [%0], [%1], 16;" :: "r"(dst), "l"(src));
}
__device__ __forceinline__ void cp_commit() {
    asm volatile("cp.async.commit_group;" ::: "memory");
}

__device__ __forceinline__ void mbar_init(uint32_t bar, uint32_t cnt) {
    asm volatile("mbarrier.init.shared.b64 [%0], %1;" :: "r"(bar), "r"(cnt) : "memory");
}
__device__ __forceinline__ void mbar_arrive(uint32_t bar) {
    asm volatile("mbarrier.arrive.shared.b64 _, [%0];" :: "r"(bar) : "memory");
}
__device__ __forceinline__ void mbar_wait(uint32_t bar, uint32_t parity) {
    asm volatile(
        "{\n\t"
        ".reg .pred P;\n\t"
        "WAITL_%=:\n\t"
        "mbarrier.try_wait.parity.shared.b64 P, [%0], %1;\n\t"
        "@P bra.uni DONEL_%=;\n\t"
        "bra.uni WAITL_%=;\n\t"
        "DONEL_%=:\n\t"
        "}"
        :: "r"(bar), "r"(parity) : "memory");
}

__device__ __forceinline__ void ldsm_x4(uint32_t& r0, uint32_t& r1, uint32_t& r2, uint32_t& r3,
                                        uint32_t addr) {
    asm volatile("ldmatrix.sync.aligned.m8n8.x4.shared.b16 {%0,%1,%2,%3}, [%4];"
                 : "=r"(r0), "=r"(r1), "=r"(r2), "=r"(r3) : "r"(addr));
}

__device__ __forceinline__ void mma_16816(float& c0, float& c1, float& c2, float& c3,
                                          uint32_t a0, uint32_t a1, uint32_t a2, uint32_t a3,
                                          uint32_t b0, uint32_t b1) {
    asm volatile(
        "mma.sync.aligned.m16n8k16.row.col.f32.f16.f16.f32 "
        "{%0,%1,%2,%3}, {%4,%5,%6,%7}, {%8,%9}, {%0,%1,%2,%3};"
        : "+f"(c0), "+f"(c1), "+f"(c2), "+f"(c3)
        : "r"(a0), "r"(a1), "r"(a2), "r"(a3), "r"(b0), "r"(b1));
}

// ---------------------------------------------------------------------------
// Fused prep: fp32 -> fp16 for x (copy) and w_t (transpose to [N][K]).
// ---------------------------------------------------------------------------
#define XV4_PER_THREAD 8
#define XBLOCKS ((MDIM * (size_t)KDIM) / 4 / 256 / XV4_PER_THREAD)   // 4096
#define WBLOCKS ((NDIM / 64) * (KDIM / 64))                          // 4096

__global__ void prep_kernel(const float* __restrict__ x, const float* __restrict__ wt) {
    __shared__ float t[64][65];
    const unsigned b = blockIdx.x;
    const int tid = threadIdx.x;
    if (b < (unsigned)XBLOCKS) {
        const float4* x4 = reinterpret_cast<const float4*>(x);
        __half2* A2 = reinterpret_cast<__half2*>(g_A);
        size_t base = (size_t)b * 256 * XV4_PER_THREAD + tid;
        float4 v[XV4_PER_THREAD];
#pragma unroll
        for (int j = 0; j < XV4_PER_THREAD; j++)
            v[j] = x4[base + (size_t)j * 256];
#pragma unroll
        for (int j = 0; j < XV4_PER_THREAD; j++) {
            size_t i = base + (size_t)j * 256;
            A2[i * 2 + 0] = __floats2half2_rn(v[j].x, v[j].y);
            A2[i * 2 + 1] = __floats2half2_rn(v[j].z, v[j].w);
        }
    } else {
        const unsigned wb = b - (unsigned)XBLOCKS;
        const int n0 = (int)(wb % (NDIM / 64)) * 64;
        const int k0 = (int)(wb / (NDIM / 64)) * 64;
        const int tx = tid & 63;
        const int ty = tid >> 6;
#pragma unroll
        for (int j = 0; j < 16; j++)
            t[ty + j * 4][tx] = wt[(size_t)(k0 + ty + j * 4) * NDIM + n0 + tx];
        __syncthreads();
        const int nl = tid >> 3;
        const int kl = (tid & 7) * 8;
#pragma unroll
        for (int pass = 0; pass < 2; pass++) {
            const int n = nl + pass * 32;
            uint4 v;
            __half2 h0 = __floats2half2_rn(t[kl + 0][n], t[kl + 1][n]);
            __half2 h1 = __floats2half2_rn(t[kl + 2][n], t[kl + 3][n]);
            __half2 h2 = __floats2half2_rn(t[kl + 4][n], t[kl + 5][n]);
            __half2 h3 = __floats2half2_rn(t[kl + 6][n], t[kl + 7][n]);
            v.x = *reinterpret_cast<uint32_t*>(&h0);
            v.y = *reinterpret_cast<uint32_t*>(&h1);
            v.z = *reinterpret_cast<uint32_t*>(&h2);
            v.w = *reinterpret_cast<uint32_t*>(&h3);
            *reinterpret_cast<uint4*>(g_B + (size_t)(n0 + n) * KDIM + k0 + kl) = v;
        }
    }
}

// ---------------------------------------------------------------------------
// Single fp16 GEMM, fp32 accumulate — barrier-free mbarrier pipeline.
// CTA 128x128, 8 warps (2x4), warp tile 64x32, KC=64, 3 stages, 2 CTAs/SM.
// All-lane mbarrier arrives (count 256).  Inner loop streams A fragments:
// B first (2 ldsm), then per mf: 1 ldsm + 4 mma — single live A fragment
// frees ~12 regs under the 128 cap and lets the first mma issue after only
// 3 ldsm instead of 6.
// ---------------------------------------------------------------------------
__global__ void __launch_bounds__(256, 2)
gemm_kernel(float* __restrict__ out) {
    extern __shared__ char smem[];
    const uint32_t sbase = smem_u32(smem);
    const uint32_t barb = sbase + STAGES * STAGE_BYTES;
    // barriers: full[s] at barb + s*16, empty[s] at barb + s*16 + 8

    const int tid = threadIdx.x;
    const int wid = tid >> 5;
    const int lid = tid & 31;
    const int wm = wid & 1;       // M offset wm*64
    const int wn = wid >> 1;      // N offset wn*32

    const int m0 = blockIdx.y * TILE_M;
    const int n0 = blockIdx.x * TILE_N;

    if (tid == 0) {
#pragma unroll
        for (int s = 0; s < STAGES; s++) {
            mbar_init(barb + s * 16, 256);      // full: every thread arrives
            mbar_init(barb + s * 16 + 8, 256);  // empty: every thread arrives
        }
    }

    // ---- load mapping: granule g -> (row = g>>3, c16 = g&7), 128B rows ----
    uint32_t a_sw[4], b_sw[4];
    uint32_t a_go[4], b_go[4];
#pragma unroll
    for (int j = 0; j < 4; j++) {
        int g = tid + j * 256;
        int r = g >> 3, c16 = g & 7;
        uint32_t sw = (uint32_t)(r * 128 + ((c16 * 16) ^ ((r & 7) << 4)));
        a_sw[j] = sw;
        b_sw[j] = A_STAGE_BYTES + sw;
        a_go[j] = (uint32_t)((m0 + r) * KDIM + c16 * 8);
        b_go[j] = (uint32_t)((n0 + r) * KDIM + c16 * 8);
    }

    // ---- ldmatrix per-lane address components ----
    const int a_row_l = lid & 15;
    const int a_kb_l = ((lid >> 4) & 1) * 16;
    const int b_row_l = (lid & 7) + ((lid >> 4) & 1) * 8;
    const int b_kb_l = ((lid >> 3) & 1) * 16;

    uint32_t a_rowterm[4], a_xr[4];
#pragma unroll
    for (int mf = 0; mf < 4; mf++) {
        int r = wm * 64 + mf * 16 + a_row_l;
        a_rowterm[mf] = (uint32_t)(r * 128);
        a_xr[mf] = (uint32_t)((r & 7) << 4);
    }
    uint32_t b_rowterm[2], b_xr[2];
#pragma unroll
    for (int p = 0; p < 2; p++) {
        int r = wn * 32 + p * 16 + b_row_l;
        b_rowterm[p] = (uint32_t)(A_STAGE_BYTES + r * 128);
        b_xr[p] = (uint32_t)((r & 7) << 4);
    }

    float acc[4][4][4];
#pragma unroll
    for (int i = 0; i < 4; i++)
#pragma unroll
        for (int j = 0; j < 4; j++)
#pragma unroll
            for (int q = 0; q < 4; q++) acc[i][j][q] = 0.f;

    auto issue_loads = [&](int cc) {
        const uint32_t k0 = (uint32_t)(cc * KC);
        const uint32_t stage = sbase + (uint32_t)(cc % STAGES) * STAGE_BYTES;
#pragma unroll
        for (int j = 0; j < 4; j++) cp_async16(stage + a_sw[j], g_A + a_go[j] + k0);
#pragma unroll
        for (int j = 0; j < 4; j++) cp_async16(stage + b_sw[j], g_B + b_go[j] + k0);
        cp_commit();
    };

    __syncthreads();   // barrier init visible before any arrive

    // prologue: stages 0,1 in flight (fresh stages: no empty wait needed)
    issue_loads(0);
    issue_loads(1);

    // cursors (explicit stage+phase bookkeeping)
    int e_stage = 0, e_phase = 0;   // producer empty-waits
    int f_phase = 0;                // consumer full-wait phase; stage = c_stage
    int c_stage = 0;                // c % STAGES without modulo

    for (int c = 0; c < NCHUNKS; c++) {
        // ---- produce chunk c+2; retire chunk c's groups; signal full(c) ----
        if (c + 2 < NCHUNKS) {
            if (c + 2 >= 3) {
                // stage (c+2)%3 reused: wait consumers done reading chunk c-1
                mbar_wait(barb + e_stage * 16 + 8, (uint32_t)e_phase);
                if (++e_stage == STAGES) { e_stage = 0; e_phase ^= 1; }
            }
            issue_loads(c + 2);
            // outstanding groups: c, c+1, c+2 -> keep 2, retire chunk c
            asm volatile("cp.async.wait_group 2;" ::: "memory");
        } else if (c + 1 < NCHUNKS) {
            asm volatile("cp.async.wait_group 1;" ::: "memory");
        } else {
            asm volatile("cp.async.wait_group 0;" ::: "memory");
        }
        mbar_arrive(barb + c_stage * 16);    // full(c): this thread's slice retired

        // ---- consume chunk c ----
        mbar_wait(barb + c_stage * 16, (uint32_t)f_phase);

        const uint32_t stage = sbase + (uint32_t)c_stage * STAGE_BYTES;
#pragma unroll
        for (int ks = 0; ks < 4; ks++) {
            const uint32_t a_kx = (uint32_t)(a_kb_l + ks * 32);
            const uint32_t b_kx = (uint32_t)(b_kb_l + ks * 32);

            // B fragments first (shared by all mf)
            uint32_t b[2][4];
#pragma unroll
            for (int p = 0; p < 2; p++)
                ldsm_x4(b[p][0], b[p][1], b[p][2], b[p][3],
                        stage + b_rowterm[p] + (b_kx ^ b_xr[p]));

            // Stream A: one fragment live at a time; mma(mf) issues while
            // the next ldsm can slot under the running mma chain.
#pragma unroll
            for (int mf = 0; mf < 4; mf++) {
                uint32_t a0, a1, a2, a3;
                ldsm_x4(a0, a1, a2, a3,
                        stage + a_rowterm[mf] + (a_kx ^ a_xr[mf]));
#pragma unroll
                for (int nf = 0; nf < 4; nf++)
                    mma_16816(acc[mf][nf][0], acc[mf][nf][1], acc[mf][nf][2], acc[mf][nf][3],
                              a0, a1, a2, a3,
                              b[nf >> 1][(nf & 1) * 2], b[nf >> 1][(nf & 1) * 2 + 1]);
            }
        }

        mbar_arrive(barb + c_stage * 16 + 8);  // empty(c): this thread done reading

        if (++c_stage == STAGES) { c_stage = 0; f_phase ^= 1; }
    }

    // ---- epilogue: fp32 acc -> gmem ----
    const int row_base = m0 + wm * 64 + (lid >> 2);
    const int col_base = n0 + wn * 32 + (lid & 3) * 2;
#pragma unroll
    for (int mf = 0; mf < 4; mf++) {
#pragma unroll
        for (int nf = 0; nf < 4; nf++) {
            int r = row_base + mf * 16;
            int cl = col_base + nf * 8;
            float2* o0 = reinterpret_cast<float2*>(out + (size_t)r * NDIM + cl);
            float2* o1 = reinterpret_cast<float2*>(out + (size_t)(r + 8) * NDIM + cl);
            *o0 = make_float2(acc[mf][nf][0], acc[mf][nf][1]);
            *o1 = make_float2(acc[mf][nf][2], acc[mf][nf][3]);
        }
    }
}

// ---------------------------------------------------------------------------
// Launch
// ---------------------------------------------------------------------------
extern "C" void kernel_launch(void* const* d_in, const int* in_sizes, int n_in,
                              void* d_out, int out_size) {
    // Identify inputs by unique element counts: x = 8192*4096, w_t = 4096*4096
    const float* x = nullptr;
    const float* wt = nullptr;
    for (int i = 0; i < n_in; i++) {
        if (in_sizes[i] == 33554432) x = (const float*)d_in[i];
        else if (in_sizes[i] == 16777216) wt = (const float*)d_in[i];
    }

    cudaFuncSetAttribute(gemm_kernel, cudaFuncAttributeMaxDynamicSharedMemorySize, SMEM_BYTES);

    prep_kernel<<<(unsigned)(XBLOCKS + WBLOCKS), 256>>>(x, wt);
    gemm_kernel<<<dim3(NDIM / TILE_N, MDIM / TILE_M), 256, SMEM_BYTES>>>((float*)d_out);
}